// round 13
// baseline (speedup 1.0000x reference)
#include <cuda_runtime.h>
#include <math.h>

#define FEAT   64
#define EMBC   256
#define IMGSZ  1024
#define NCELLS 256
#define THRESH 0.65f
#define SCAN_BX 15
#define SCAN_BY 69
#define TILE_R  16
#define TILE_C  80
#define YCHUNK  40

// ---------------- device scratch (no allocations allowed) ----------------
__device__ float d_sim[FEAT * FEAT];
__device__ float4 d_xtab[4096];              // scan x-taps: {i0 (bits), w0, w1, 0}
__device__ float4 d_ytab[4096];              // scan y-taps: {i0 (bits), w0, w1, gy16 (bits)}
__device__ float4 d_xt1[1024];               // 64->1024 taps (P rows AND cols)
__device__ unsigned long long d_minkey;      // global argmin key
__device__ unsigned long long d_cellkey[NCELLS];
__device__ int d_counter;

// ---------------- ordered-float key helpers ----------------
__device__ __forceinline__ unsigned fkey(float f) {
    unsigned u = __float_as_uint(f);
    return (u >> 31) ? ~u : (u | 0x80000000u);   // monotone: smaller float -> smaller key
}
__device__ __forceinline__ float unfkey(unsigned k) {
    return (k & 0x80000000u) ? __uint_as_float(k & 0x7FFFFFFFu) : __uint_as_float(~k);
}

// ---------------- jax.image.resize (linear, antialias=False) fp-exact taps ----------------
struct Tap { int i0; float w0, w1; };

__device__ __forceinline__ float samplef(int o, float inv) {
    return __fsub_rn(__fmul_rn(__fadd_rn((float)o, 0.5f), inv), 0.5f);
}

__device__ __forceinline__ Tap make_tap(float s, int n) {
    Tap t;
    float fs = floorf(s);
    int i0 = (int)fs;
    if (i0 < 0)            { t.i0 = 0;     t.w0 = 1.f; t.w1 = 0.f; }
    else if (i0 >= n - 1)  { t.i0 = n - 2; t.w0 = 0.f; t.w1 = 1.f; }
    else {
        float w0  = __fsub_rn(1.0f, __fsub_rn(s, fs));
        float w1  = __fsub_rn(1.0f, __fsub_rn((float)(i0 + 1), s));
        float sum = __fadd_rn(w0, w1);
        if (sum != 1.0f) { w0 = __fdiv_rn(w0, sum); w1 = __fdiv_rn(w1, sum); }
        t.i0 = i0; t.w0 = w0; t.w1 = w1;
    }
    return t;
}

// P(r,c) with the exact k_prep expression (bit-identical wherever computed)
__device__ __forceinline__ float p_val(int pr, int pc) {
    float4 tyr = d_xt1[pr];
    float4 txc = d_xt1[pc];
    int yi = __float_as_int(tyr.x);
    int xi = __float_as_int(txc.x);
    const float* s0 = d_sim + yi * FEAT;
    float cy0 = fmaf(tyr.z, s0[FEAT + xi],     __fmul_rn(tyr.y, s0[xi]));
    float cy1 = fmaf(tyr.z, s0[FEAT + xi + 1], __fmul_rn(tyr.y, s0[xi + 1]));
    return fmaf(txc.z, cy1, __fmul_rn(txc.y, cy0));
}

// ---------------- kernel 1: sim (8-way channel split) + all tap tables + init ----------------
__global__ void __launch_bounds__(256) k_simtab(const float* __restrict__ emb,
                                                const float* __restrict__ ref,
                                                const int* __restrict__ ori) {
    int t = threadIdx.x;
    if (blockIdx.x < 128) {
        __shared__ float sref[EMBC];
        __shared__ float sdot[256];
        __shared__ float snrm[256];
        sref[t] = ref[t];
        __syncthreads();

        int px = t & 31;
        int q  = t >> 5;                      // channel group 0..7
        int p  = (blockIdx.x << 5) + px;      // feature pixel
        const float* e = emb + (q * 32) * (FEAT * FEAT) + p;
        const float* r = sref + q * 32;
        float dot = 0.f, nrm = 0.f;
        #pragma unroll
        for (int j = 0; j < 32; j++) {
            float v = e[j * (FEAT * FEAT)];   // coalesced, 32 independent loads
            dot = fmaf(r[j], v, dot);
            nrm = fmaf(v, v, nrm);
        }
        sdot[t] = dot; snrm[t] = nrm;
        __syncthreads();

        if (t < 32) {
            float D = sdot[t], N = snrm[t];
            #pragma unroll
            for (int q2 = 1; q2 < 8; q2++) {  // fixed sequential order (deterministic)
                D += sdot[t + (q2 << 5)];
                N += snrm[t + (q2 << 5)];
            }
            d_sim[(blockIdx.x << 5) + t] = D / sqrtf(N);
        }
    } else {
        int idx = (blockIdx.x - 128) * 256 + t;   // 0..4095
        if (idx == 0) { d_minkey = ~0ull; d_counter = 0; }
        if (idx < NCELLS) d_cellkey[idx] = 0ull;

        if (idx < 1024) {                         // 64 -> 1024 taps (P rows and cols)
            Tap tp = make_tap(samplef(idx, 0.0625f), FEAT);
            d_xt1[idx] = make_float4(__int_as_float(tp.i0), tp.w0, tp.w1, 0.f);
        }
        int H = ori[0], W = ori[1];
        int mx = max(H, W);
        double scale = (double)IMGSZ / (double)mx;
        int ph = (int)floor((double)H * scale + 0.5);
        int pw = (int)floor((double)W * scale + 0.5);
        float invx = (float)(1.0 / ((double)W / (double)pw));
        float invy = (float)(1.0 / ((double)H / (double)ph));
        float r64  = (float)(scale / 64.0);
        if (idx < W) {                            // scan x-taps (pw -> W)
            Tap tp = make_tap(samplef(idx, invx), pw);
            d_xtab[idx] = make_float4(__int_as_float(tp.i0), tp.w0, tp.w1, 0.f);
        }
        if (idx < H) {                            // scan y-taps (ph -> H) + gy16
            Tap tp = make_tap(samplef(idx, invy), ph);
            int gy16 = 16 * (int)floorf(__fmul_rn((float)idx, r64));
            d_ytab[idx] = make_float4(__int_as_float(tp.i0), tp.w0, tp.w1,
                                      __int_as_float(gy16));
        }
    }
}

// ---------------- kernel 2: fused P-tile + value-only column scan + finalize ----------------
// Hot loop tracks only min/max VALUES (FMNMX-class, no predicated selects).
// The argmin index is recovered afterwards by a cheap targeted re-scan.
__global__ void __launch_bounds__(256, 7) k_scan(const int* __restrict__ ori,
                                                 float* __restrict__ out) {
    int H = ori[0], W = ori[1];
    int mx = max(H, W);
    double scale = (double)IMGSZ / (double)mx;
    float r64  = (float)(scale / 64.0);

    __shared__ float2 tile2[TILE_R][TILE_C];   // {P(r,c), P(r,c+1)} pairs
    __shared__ float4 s_yt[YCHUNK];            // staged y-taps for this strip
    __shared__ unsigned long long sk[256];     // also reused for 32-bit key reduce
    __shared__ unsigned s_bk;
    __shared__ int s_last;

    int t  = threadIdx.x;
    int xs = blockIdx.x * 256;
    int nby = gridDim.y;
    int chn = (H + nby - 1) / nby;             // <= YCHUNK
    int ys = blockIdx.y * chn;
    int ye = min(H, ys + chn);

    unsigned long long localkey = ~0ull;

    if (ys < H && xs < W) {
        int ny = ye - ys;
        int xe = min(xs + 256, W);
        // P-tile bounds this block needs (monotone tap tables)
        int pr0 = __float_as_int(d_ytab[ys].x);
        int pr1 = __float_as_int(d_ytab[ye - 1].x) + 1;
        int px0 = __float_as_int(d_xtab[xs].x);
        int px1 = __float_as_int(d_xtab[xe - 1].x) + 1;
        int NR = pr1 - pr0 + 1;            // <= 12
        int NC = px1 - px0 + 1;            // <= 70

        // stage y-taps for this strip
        for (int i = t; i < ny; i += 256) s_yt[i] = d_ytab[ys + i];

        // build tile2: each entry holds (P(r,c), P(r,c+1)), exact expression
        int nbuild = NR * (NC - 1);
        for (int i = t; i < nbuild; i += 256) {
            int r = i / (NC - 1), c = i - r * (NC - 1);
            float v0 = p_val(pr0 + r, px0 + c);
            float v1 = p_val(pr0 + r, px0 + c + 1);
            tile2[r][c] = make_float2(v0, v1);
        }
        __syncthreads();

        int x = xs + t;
        unsigned mykey = 0xFFFFFFFFu;
        float wx0 = 0.f, wx1 = 0.f;
        int lx = 0;
        float rmax = -INFINITY;

        if (x < W) {
            float4 tx = d_xtab[x];
            lx  = __float_as_int(tx.x) - px0;
            wx0 = tx.y; wx1 = tx.z;

            // 4 independent value-only min chains + max chains (branch-free)
            float rb0 = INFINITY, rb1 = INFINITY, rb2 = INFINITY, rb3 = INFINITY;
            float rx0 = -INFINITY, rx1 = -INFINITY;

            int i = 0;
            for (; i + 3 < ny; i += 4) {
                #pragma unroll
                for (int j = 0; j < 4; j++) {
                    float4 ty = s_yt[i + j];
                    int lr = __float_as_int(ty.x) - pr0;
                    float2 A = tile2[lr][lx];
                    float2 B = tile2[lr + 1][lx];
                    float c0 = fmaf(ty.z, B.x, __fmul_rn(ty.y, A.x));
                    float c1 = fmaf(ty.z, B.y, __fmul_rn(ty.y, A.y));
                    float v  = fmaf(wx1, c1, __fmul_rn(wx0, c0));
                    if (j == 0) rb0 = fminf(rb0, v);
                    if (j == 1) rb1 = fminf(rb1, v);
                    if (j == 2) rb2 = fminf(rb2, v);
                    if (j == 3) rb3 = fminf(rb3, v);
                    if (j & 1) rx1 = fmaxf(rx1, v); else rx0 = fmaxf(rx0, v);
                }
            }
            for (; i < ny; i++) {
                float4 ty = s_yt[i];
                int lr = __float_as_int(ty.x) - pr0;
                float2 A = tile2[lr][lx];
                float2 B = tile2[lr + 1][lx];
                float c0 = fmaf(ty.z, B.x, __fmul_rn(ty.y, A.x));
                float c1 = fmaf(ty.z, B.y, __fmul_rn(ty.y, A.y));
                float v  = fmaf(wx1, c1, __fmul_rn(wx0, c0));
                rb0 = fminf(rb0, v);
                rx0 = fmaxf(rx0, v);
            }
            rmax = fmaxf(rx0, rx1);

            // min over chains in key space (consistent ordering incl. -0/+0)
            mykey = min(min(fkey(rb0), fkey(rb1)), min(fkey(rb2), fkey(rb3)));

            // rare slow path: threshold atomics (identical values & atomics)
            if (rmax > THRESH) {
                int gx = (int)floorf(__fmul_rn((float)x, r64));
                int idx = ys * W + x;
                for (int k = 0; k < ny; k++) {
                    float4 ty = s_yt[k];
                    int lr = __float_as_int(ty.x) - pr0;
                    float2 A = tile2[lr][lx];
                    float2 B = tile2[lr + 1][lx];
                    float c0 = fmaf(ty.z, B.x, __fmul_rn(ty.y, A.x));
                    float c1 = fmaf(ty.z, B.y, __fmul_rn(ty.y, A.y));
                    float v  = fmaf(wx1, c1, __fmul_rn(wx0, c0));
                    if (v > THRESH) {
                        int cell = __float_as_int(ty.w) + gx;
                        unsigned long long ck = ((unsigned long long)fkey(v) << 32)
                                              | (unsigned)(0xFFFFFFFFu - (unsigned)idx);
                        atomicMax(&d_cellkey[cell], ck);
                    }
                    idx += W;
                }
            }
        }

        // 32-bit block min of value keys
        sk[t] = mykey;
        __syncthreads();
        for (int o = 128; o > 0; o >>= 1) {
            if (t < o) sk[t] = min(sk[t], sk[t + o]);
            __syncthreads();
        }
        if (t == 0) s_bk = (unsigned)sk[0];
        __syncthreads();
        unsigned bk = s_bk;

        // only matching threads (≈1) re-scan for the FIRST bit-equal hit
        if (x < W && mykey == bk) {
            int idx = ys * W + x;
            for (int k = 0; k < ny; k++) {
                float4 ty = s_yt[k];
                int lr = __float_as_int(ty.x) - pr0;
                float2 A = tile2[lr][lx];
                float2 B = tile2[lr + 1][lx];
                float c0 = fmaf(ty.z, B.x, __fmul_rn(ty.y, A.x));
                float c1 = fmaf(ty.z, B.y, __fmul_rn(ty.y, A.y));
                float v  = fmaf(wx1, c1, __fmul_rn(wx0, c0));
                if (fkey(v) == bk) { localkey = ((unsigned long long)bk << 32) | (unsigned)idx; break; }
                idx += W;
            }
        }
    }

    // 64-bit block reduction of (value,idx) keys -> lowest idx on ties
    __syncthreads();
    sk[t] = localkey;
    __syncthreads();
    for (int o = 128; o > 0; o >>= 1) {
        if (t < o) sk[t] = min(sk[t], sk[t + o]);
        __syncthreads();
    }
    if (t == 0) {
        atomicMin(&d_minkey, sk[0]);
        __threadfence();
        s_last = (atomicAdd(&d_counter, 1) == (int)(gridDim.x * gridDim.y) - 1);
    }
    __syncthreads();
    if (!s_last) return;

    // ---- last block: finalize ----
    __shared__ float s_key[NCELLS];
    unsigned long long ck = atomicOr(&d_cellkey[t], 0ull);    // coherent read
    bool valid = (ck != 0ull);
    float ps = 0.f; int pidx = 0;
    if (valid) {
        ps   = unfkey((unsigned)(ck >> 32));
        pidx = (int)(0xFFFFFFFFu - (unsigned)(ck & 0xFFFFFFFFull));
    }
    float skey = valid ? ps : -INFINITY;
    s_key[t] = skey;
    __syncthreads();

    int rank = 0;
    #pragma unroll 8
    for (int j = 0; j < NCELLS; j++) {
        float o = s_key[j];
        rank += (o > skey) || (o == skey && j < t);
    }

    out[rank * 3 + 0] = valid ? (float)(pidx % W) : -1.f;
    out[rank * 3 + 1] = valid ? (float)(pidx / W) : -1.f;
    out[rank * 3 + 2] = valid ? ps : -1.f;

    if (t == 0) {
        unsigned long long mk = atomicOr(&d_minkey, 0ull);
        unsigned bidx = (unsigned)(mk & 0xFFFFFFFFull);
        out[NCELLS * 3 + 0] = (float)(bidx % (unsigned)W);   // bg col (x)
        out[NCELLS * 3 + 1] = (float)(bidx / (unsigned)W);   // bg row (y)
    }
}

// ---------------- launch ----------------
extern "C" void kernel_launch(void* const* d_in, const int* in_sizes, int n_in,
                              void* d_out, int out_size) {
    int ie = 0, ir = 1, io = 2;
    for (int i = 0; i < n_in; i++) {
        if (in_sizes[i] == 2) io = i;
        else if (in_sizes[i] == EMBC) ir = i;
        else ie = i;
    }
    const float* emb = (const float*)d_in[ie];
    const float* ref = (const float*)d_in[ir];
    const int*   ori = (const int*)d_in[io];
    float* out = (float*)d_out;

    k_simtab<<<144, 256>>>(emb, ref, ori);
    k_scan  <<<dim3(SCAN_BX, SCAN_BY), 256>>>(ori, out);
}

// round 15
// speedup vs baseline: 1.1488x; 1.1488x over previous
#include <cuda_runtime.h>
#include <math.h>

#define FEAT   64
#define EMBC   256
#define IMGSZ  1024
#define NCELLS 256
#define THRESH 0.65f
#define SCAN_BX 8
#define SCAN_BY 90
#define TILE_R  16
#define TILE_C  144
#define YCHUNK  64

// ---------------- device scratch (no allocations allowed) ----------------
__device__ float d_sim[FEAT * FEAT];
__device__ float4 d_xtab[4096];              // scan x-taps: {i0 (bits), w0, w1, 0}
__device__ float4 d_ytab[4096];              // scan y-taps: {i0 (bits), w0, w1, gy16 (bits)}
__device__ float4 d_xt1[1024];               // 64->1024 taps (P rows AND cols)
__device__ unsigned long long d_minkey;      // global argmin key
__device__ unsigned long long d_cellkey[NCELLS];
__device__ int d_counter;

// ---------------- ordered-float key helpers ----------------
__device__ __forceinline__ unsigned fkey(float f) {
    unsigned u = __float_as_uint(f);
    return (u >> 31) ? ~u : (u | 0x80000000u);   // monotone: smaller float -> smaller key
}
__device__ __forceinline__ float unfkey(unsigned k) {
    return (k & 0x80000000u) ? __uint_as_float(k & 0x7FFFFFFFu) : __uint_as_float(~k);
}

// ---------------- jax.image.resize (linear, antialias=False) fp-exact taps ----------------
struct Tap { int i0; float w0, w1; };

__device__ __forceinline__ float samplef(int o, float inv) {
    return __fsub_rn(__fmul_rn(__fadd_rn((float)o, 0.5f), inv), 0.5f);
}

__device__ __forceinline__ Tap make_tap(float s, int n) {
    Tap t;
    float fs = floorf(s);
    int i0 = (int)fs;
    if (i0 < 0)            { t.i0 = 0;     t.w0 = 1.f; t.w1 = 0.f; }
    else if (i0 >= n - 1)  { t.i0 = n - 2; t.w0 = 0.f; t.w1 = 1.f; }
    else {
        float w0  = __fsub_rn(1.0f, __fsub_rn(s, fs));
        float w1  = __fsub_rn(1.0f, __fsub_rn((float)(i0 + 1), s));
        float sum = __fadd_rn(w0, w1);
        if (sum != 1.0f) { w0 = __fdiv_rn(w0, sum); w1 = __fdiv_rn(w1, sum); }
        t.i0 = i0; t.w0 = w0; t.w1 = w1;
    }
    return t;
}

// P(r,c) with the exact k_prep expression (bit-identical wherever computed)
__device__ __forceinline__ float p_val(int pr, int pc) {
    float4 tyr = d_xt1[pr];
    float4 txc = d_xt1[pc];
    int yi = __float_as_int(tyr.x);
    int xi = __float_as_int(txc.x);
    const float* s0 = d_sim + yi * FEAT;
    float cy0 = fmaf(tyr.z, s0[FEAT + xi],     __fmul_rn(tyr.y, s0[xi]));
    float cy1 = fmaf(tyr.z, s0[FEAT + xi + 1], __fmul_rn(tyr.y, s0[xi + 1]));
    return fmaf(txc.z, cy1, __fmul_rn(txc.y, cy0));
}

// ---------------- kernel 1: sim (8-way channel split) + all tap tables + init ----------------
__global__ void __launch_bounds__(256) k_simtab(const float* __restrict__ emb,
                                                const float* __restrict__ ref,
                                                const int* __restrict__ ori) {
    int t = threadIdx.x;
    if (blockIdx.x < 128) {
        __shared__ float sref[EMBC];
        __shared__ float sdot[256];
        __shared__ float snrm[256];
        sref[t] = ref[t];
        __syncthreads();

        int px = t & 31;
        int q  = t >> 5;                      // channel group 0..7
        int p  = (blockIdx.x << 5) + px;      // feature pixel
        const float* e = emb + (q * 32) * (FEAT * FEAT) + p;
        const float* r = sref + q * 32;
        float dot = 0.f, nrm = 0.f;
        #pragma unroll
        for (int j = 0; j < 32; j++) {
            float v = e[j * (FEAT * FEAT)];   // coalesced, 32 independent loads
            dot = fmaf(r[j], v, dot);
            nrm = fmaf(v, v, nrm);
        }
        sdot[t] = dot; snrm[t] = nrm;
        __syncthreads();

        if (t < 32) {
            float D = sdot[t], N = snrm[t];
            #pragma unroll
            for (int q2 = 1; q2 < 8; q2++) {  // fixed sequential order (deterministic)
                D += sdot[t + (q2 << 5)];
                N += snrm[t + (q2 << 5)];
            }
            d_sim[(blockIdx.x << 5) + t] = D / sqrtf(N);
        }
    } else {
        int idx = (blockIdx.x - 128) * 256 + t;   // 0..4095
        if (idx == 0) { d_minkey = ~0ull; d_counter = 0; }
        if (idx < NCELLS) d_cellkey[idx] = 0ull;

        if (idx < 1024) {                         // 64 -> 1024 taps (P rows and cols)
            Tap tp = make_tap(samplef(idx, 0.0625f), FEAT);
            d_xt1[idx] = make_float4(__int_as_float(tp.i0), tp.w0, tp.w1, 0.f);
        }
        int H = ori[0], W = ori[1];
        int mx = max(H, W);
        double scale = (double)IMGSZ / (double)mx;
        int ph = (int)floor((double)H * scale + 0.5);
        int pw = (int)floor((double)W * scale + 0.5);
        float invx = (float)(1.0 / ((double)W / (double)pw));
        float invy = (float)(1.0 / ((double)H / (double)ph));
        float r64  = (float)(scale / 64.0);
        if (idx < W) {                            // scan x-taps (pw -> W)
            Tap tp = make_tap(samplef(idx, invx), pw);
            d_xtab[idx] = make_float4(__int_as_float(tp.i0), tp.w0, tp.w1, 0.f);
        }
        if (idx < H) {                            // scan y-taps (ph -> H) + gy16
            Tap tp = make_tap(samplef(idx, invy), ph);
            int gy16 = 16 * (int)floorf(__fmul_rn((float)idx, r64));
            d_ytab[idx] = make_float4(__int_as_float(tp.i0), tp.w0, tp.w1,
                                      __int_as_float(gy16));
        }
    }
}

// ---------------- kernel 2: fused P-tile + 2-column scan + finalize ----------------
// Each thread scans TWO output columns (x, x+256); warp-uniform y-tap load and
// row addressing amortized across both. 2 index-tracked min chains per column.
__global__ void __launch_bounds__(256, 6) k_scan(const int* __restrict__ ori,
                                                 float* __restrict__ out) {
    int H = ori[0], W = ori[1];
    int mx = max(H, W);
    double scale = (double)IMGSZ / (double)mx;
    float r64  = (float)(scale / 64.0);

    __shared__ float2 tile2[TILE_R][TILE_C];   // {P(r,c), P(r,c+1)} pairs
    __shared__ float4 s_yt[YCHUNK];            // staged y-taps for this strip

    int t  = threadIdx.x;
    int xs = blockIdx.x * 512;
    int nby = gridDim.y;
    int chn = (H + nby - 1) / nby;             // <= YCHUNK
    int ys = blockIdx.y * chn;
    int ye = min(H, ys + chn);

    unsigned long long localkey = ~0ull;

    if (ys < H && xs < W) {
        int ny = ye - ys;
        int xe = min(xs + 512, W);
        // P-tile bounds this block needs (monotone tap tables)
        int pr0 = __float_as_int(d_ytab[ys].x);
        int pr1 = __float_as_int(d_ytab[ye - 1].x) + 1;
        int px0 = __float_as_int(d_xtab[xs].x);
        int px1 = __float_as_int(d_xtab[xe - 1].x) + 1;
        int NR = pr1 - pr0 + 1;            // <= ~10
        int NC = px1 - px0 + 1;            // <= ~140

        // stage y-taps for this strip
        for (int i = t; i < ny; i += 256) s_yt[i] = d_ytab[ys + i];

        // build tile2: each entry holds (P(r,c), P(r,c+1)), exact expression
        int nbuild = NR * (NC - 1);
        for (int i = t; i < nbuild; i += 256) {
            int r = i / (NC - 1), c = i - r * (NC - 1);
            float v0 = p_val(pr0 + r, px0 + c);
            float v1 = p_val(pr0 + r, px0 + c + 1);
            tile2[r][c] = make_float2(v0, v1);
        }
        __syncthreads();

        int xa = xs + t;            // column A
        int xb = xa + 256;          // column B
        bool hasB = (xb < W);
        if (xa < W) {
            float4 txA = d_xtab[xa];
            int   lxa  = __float_as_int(txA.x) - px0;
            float wa0 = txA.y, wa1 = txA.z;
            float4 txB = hasB ? d_xtab[xb] : txA;
            int   lxb  = __float_as_int(txB.x) - px0;
            float wb0 = txB.y, wb1 = txB.z;

            // 2 index-tracked chains per column (even/odd y) + one shared max
            float rba0 = INFINITY, rba1 = INFINITY, rbb0 = INFINITY, rbb1 = INFINITY;
            int   ria0 = 0, ria1 = 0, rib0 = 0, rib1 = 0;
            float rmax = -INFINITY;

            int idx0 = ys * W + xa;     // column A index; column B = +256
            int i = 0;
            for (; i + 1 < ny; i += 2) {
                #pragma unroll
                for (int j = 0; j < 2; j++) {
                    float4 ty = s_yt[i + j];
                    int lr = __float_as_int(ty.x) - pr0;
                    const float2* R0 = &tile2[lr][0];
                    const float2* R1 = &tile2[lr + 1][0];
                    float2 A0 = R0[lxa], B0 = R1[lxa];
                    float2 A1 = R0[lxb], B1 = R1[lxb];

                    float ca0 = fmaf(ty.z, B0.x, __fmul_rn(ty.y, A0.x));
                    float ca1 = fmaf(ty.z, B0.y, __fmul_rn(ty.y, A0.y));
                    float va  = fmaf(wa1, ca1, __fmul_rn(wa0, ca0));

                    float cb0 = fmaf(ty.z, B1.x, __fmul_rn(ty.y, A1.x));
                    float cb1 = fmaf(ty.z, B1.y, __fmul_rn(ty.y, A1.y));
                    float vb  = fmaf(wb1, cb1, __fmul_rn(wb0, cb0));

                    int idx = idx0 + j * W;
                    if (j == 0) {
                        if (va < rba0) { rba0 = va; ria0 = idx; }
                        if (vb < rbb0) { rbb0 = vb; rib0 = idx; }
                    } else {
                        if (va < rba1) { rba1 = va; ria1 = idx; }
                        if (vb < rbb1) { rbb1 = vb; rib1 = idx; }
                    }
                    rmax = fmaxf(rmax, fmaxf(va, vb));
                }
                idx0 += 2 * W;
            }
            for (; i < ny; i++) {                // remainder -> chain 0
                float4 ty = s_yt[i];
                int lr = __float_as_int(ty.x) - pr0;
                const float2* R0 = &tile2[lr][0];
                const float2* R1 = &tile2[lr + 1][0];
                float2 A0 = R0[lxa], B0 = R1[lxa];
                float2 A1 = R0[lxb], B1 = R1[lxb];
                float ca0 = fmaf(ty.z, B0.x, __fmul_rn(ty.y, A0.x));
                float ca1 = fmaf(ty.z, B0.y, __fmul_rn(ty.y, A0.y));
                float va  = fmaf(wa1, ca1, __fmul_rn(wa0, ca0));
                float cb0 = fmaf(ty.z, B1.x, __fmul_rn(ty.y, A1.x));
                float cb1 = fmaf(ty.z, B1.y, __fmul_rn(ty.y, A1.y));
                float vb  = fmaf(wb1, cb1, __fmul_rn(wb0, cb0));
                if (va < rba0) { rba0 = va; ria0 = idx0; }
                if (vb < rbb0) { rbb0 = vb; rib0 = idx0; }
                rmax = fmaxf(rmax, fmaxf(va, vb));
                idx0 += W;
            }

            // merge: packed keys, column B indices shifted by +256 (its true x)
            unsigned long long ka0 = ((unsigned long long)fkey(rba0) << 32) | (unsigned)ria0;
            unsigned long long ka1 = ((unsigned long long)fkey(rba1) << 32) | (unsigned)ria1;
            localkey = min(ka0, ka1);
            if (hasB) {
                unsigned long long kb0 = ((unsigned long long)fkey(rbb0) << 32) | (unsigned)(rib0 + 256);
                unsigned long long kb1 = ((unsigned long long)fkey(rbb1) << 32) | (unsigned)(rib1 + 256);
                localkey = min(localkey, min(kb0, kb1));
            }

            // rare slow path: redo both columns with identical values & atomics
            if (rmax > THRESH) {
                int gxa = (int)floorf(__fmul_rn((float)xa, r64));
                int gxb = (int)floorf(__fmul_rn((float)xb, r64));
                int idx = ys * W + xa;
                for (int k = 0; k < ny; k++) {
                    float4 ty = s_yt[k];
                    int lr = __float_as_int(ty.x) - pr0;
                    const float2* R0 = &tile2[lr][0];
                    const float2* R1 = &tile2[lr + 1][0];
                    float2 A0 = R0[lxa], B0 = R1[lxa];
                    float ca0 = fmaf(ty.z, B0.x, __fmul_rn(ty.y, A0.x));
                    float ca1 = fmaf(ty.z, B0.y, __fmul_rn(ty.y, A0.y));
                    float va  = fmaf(wa1, ca1, __fmul_rn(wa0, ca0));
                    if (va > THRESH) {
                        int cell = __float_as_int(ty.w) + gxa;
                        unsigned long long ck = ((unsigned long long)fkey(va) << 32)
                                              | (unsigned)(0xFFFFFFFFu - (unsigned)idx);
                        atomicMax(&d_cellkey[cell], ck);
                    }
                    if (hasB) {
                        float2 A1 = R0[lxb], B1 = R1[lxb];
                        float cb0 = fmaf(ty.z, B1.x, __fmul_rn(ty.y, A1.x));
                        float cb1 = fmaf(ty.z, B1.y, __fmul_rn(ty.y, A1.y));
                        float vb  = fmaf(wb1, cb1, __fmul_rn(wb0, cb0));
                        if (vb > THRESH) {
                            int cell = __float_as_int(ty.w) + gxb;
                            unsigned long long ck = ((unsigned long long)fkey(vb) << 32)
                                                  | (unsigned)(0xFFFFFFFFu - (unsigned)(idx + 256));
                            atomicMax(&d_cellkey[cell], ck);
                        }
                    }
                    idx += W;
                }
            }
        }
    }

    // block argmin reduction
    __shared__ unsigned long long sk[256];
    __shared__ int s_last;
    sk[t] = localkey;
    __syncthreads();
    for (int o = 128; o > 0; o >>= 1) {
        if (t < o) sk[t] = min(sk[t], sk[t + o]);
        __syncthreads();
    }
    if (t == 0) {
        atomicMin(&d_minkey, sk[0]);
        __threadfence();
        s_last = (atomicAdd(&d_counter, 1) == (int)(gridDim.x * gridDim.y) - 1);
    }
    __syncthreads();
    if (!s_last) return;

    // ---- last block: finalize ----
    __shared__ float s_key[NCELLS];
    unsigned long long ck = atomicOr(&d_cellkey[t], 0ull);    // coherent read
    bool valid = (ck != 0ull);
    float ps = 0.f; int pidx = 0;
    if (valid) {
        ps   = unfkey((unsigned)(ck >> 32));
        pidx = (int)(0xFFFFFFFFu - (unsigned)(ck & 0xFFFFFFFFull));
    }
    float skey = valid ? ps : -INFINITY;
    s_key[t] = skey;
    __syncthreads();

    int rank = 0;
    #pragma unroll 8
    for (int j = 0; j < NCELLS; j++) {
        float o = s_key[j];
        rank += (o > skey) || (o == skey && j < t);
    }

    out[rank * 3 + 0] = valid ? (float)(pidx % W) : -1.f;
    out[rank * 3 + 1] = valid ? (float)(pidx / W) : -1.f;
    out[rank * 3 + 2] = valid ? ps : -1.f;

    if (t == 0) {
        unsigned long long mk = atomicOr(&d_minkey, 0ull);
        unsigned bidx = (unsigned)(mk & 0xFFFFFFFFull);
        out[NCELLS * 3 + 0] = (float)(bidx % (unsigned)W);   // bg col (x)
        out[NCELLS * 3 + 1] = (float)(bidx / (unsigned)W);   // bg row (y)
    }
}

// ---------------- launch ----------------
extern "C" void kernel_launch(void* const* d_in, const int* in_sizes, int n_in,
                              void* d_out, int out_size) {
    int ie = 0, ir = 1, io = 2;
    for (int i = 0; i < n_in; i++) {
        if (in_sizes[i] == 2) io = i;
        else if (in_sizes[i] == EMBC) ir = i;
        else ie = i;
    }
    const float* emb = (const float*)d_in[ie];
    const float* ref = (const float*)d_in[ir];
    const int*   ori = (const int*)d_in[io];
    float* out = (float*)d_out;

    k_simtab<<<144, 256>>>(emb, ref, ori);
    k_scan  <<<dim3(SCAN_BX, SCAN_BY), 256>>>(ori, out);
}

// round 16
// speedup vs baseline: 1.1722x; 1.0204x over previous
#include <cuda_runtime.h>
#include <math.h>

#define FEAT   64
#define EMBC   256
#define IMGSZ  1024
#define NCELLS 256
#define THRESH 0.65f
#define SCAN_BX 8
#define SCAN_BY 90
#define TILE_R  16
#define TILE_C  144
#define YCHUNK  64
#define NINIT   144
#define NBLK    (SCAN_BX * SCAN_BY)

// ---------------- device scratch (no allocations allowed) ----------------
__device__ float d_sim[FEAT * FEAT];
__device__ float4 d_xtab[4096];              // scan x-taps: {i0 (bits), w0, w1, 0}
__device__ float4 d_ytab[4096];              // scan y-taps: {i0 (bits), w0, w1, gy16 (bits)}
__device__ float4 d_xt1[1024];               // 64->1024 taps (P rows AND cols)
__device__ unsigned long long d_minkey;      // global argmin key
__device__ unsigned long long d_cellkey[NCELLS];
__device__ int d_counter = 0;                // scan-done counter (reset by last block)
__device__ int d_go = 0;                     // phase-1-done counter (reset by last block)

// ---------------- ordered-float key helpers ----------------
__device__ __forceinline__ unsigned fkey(float f) {
    unsigned u = __float_as_uint(f);
    return (u >> 31) ? ~u : (u | 0x80000000u);   // monotone: smaller float -> smaller key
}
__device__ __forceinline__ float unfkey(unsigned k) {
    return (k & 0x80000000u) ? __uint_as_float(k & 0x7FFFFFFFu) : __uint_as_float(~k);
}

// ---------------- jax.image.resize (linear, antialias=False) fp-exact taps ----------------
struct Tap { int i0; float w0, w1; };

__device__ __forceinline__ float samplef(int o, float inv) {
    return __fsub_rn(__fmul_rn(__fadd_rn((float)o, 0.5f), inv), 0.5f);
}

__device__ __forceinline__ Tap make_tap(float s, int n) {
    Tap t;
    float fs = floorf(s);
    int i0 = (int)fs;
    if (i0 < 0)            { t.i0 = 0;     t.w0 = 1.f; t.w1 = 0.f; }
    else if (i0 >= n - 1)  { t.i0 = n - 2; t.w0 = 0.f; t.w1 = 1.f; }
    else {
        float w0  = __fsub_rn(1.0f, __fsub_rn(s, fs));
        float w1  = __fsub_rn(1.0f, __fsub_rn((float)(i0 + 1), s));
        float sum = __fadd_rn(w0, w1);
        if (sum != 1.0f) { w0 = __fdiv_rn(w0, sum); w1 = __fdiv_rn(w1, sum); }
        t.i0 = i0; t.w0 = w0; t.w1 = w1;
    }
    return t;
}

// P(r,c) with the exact prep expression (bit-identical wherever computed)
__device__ __forceinline__ float p_val(int pr, int pc) {
    float4 tyr = d_xt1[pr];
    float4 txc = d_xt1[pc];
    int yi = __float_as_int(tyr.x);
    int xi = __float_as_int(txc.x);
    const float* s0 = d_sim + yi * FEAT;
    float cy0 = fmaf(tyr.z, s0[FEAT + xi],     __fmul_rn(tyr.y, s0[xi]));
    float cy1 = fmaf(tyr.z, s0[FEAT + xi + 1], __fmul_rn(tyr.y, s0[xi + 1]));
    return fmaf(txc.z, cy1, __fmul_rn(txc.y, cy0));
}

// ---------------- single fused kernel ----------------
// Phase 1 (blocks 0..143): sim + tables + init.  All 720 blocks are co-resident
// (launch_bounds(256,6) => 888 slots >= 720), so a spin on d_go is safe.
// Phase 2 (all blocks): tiled 2-column scan. Last block finalizes + resets state.
__global__ void __launch_bounds__(256, 6) k_all(const float* __restrict__ emb,
                                                const float* __restrict__ ref,
                                                const int* __restrict__ ori,
                                                float* __restrict__ out) {
    __shared__ float2 tile2[TILE_R][TILE_C];   // {P(r,c), P(r,c+1)} pairs
    __shared__ float4 s_yt[YCHUNK];            // staged y-taps for this strip
    __shared__ float sph1[768];                // phase-1 scratch (sref/sdot/snrm)

    int t   = threadIdx.x;
    int bid = blockIdx.y * gridDim.x + blockIdx.x;   // 0..719

    // ================= phase 1 =================
    if (bid < 128) {
        float* sref = sph1;
        float* sdot = sph1 + 256;
        float* snrm = sph1 + 512;
        sref[t] = ref[t];
        __syncthreads();

        int px = t & 31;
        int q  = t >> 5;                      // channel group 0..7
        int p  = (bid << 5) + px;             // feature pixel
        const float* e = emb + (q * 32) * (FEAT * FEAT) + p;
        const float* r = sref + q * 32;
        float dot = 0.f, nrm = 0.f;
        #pragma unroll
        for (int j = 0; j < 32; j++) {
            float v = e[j * (FEAT * FEAT)];   // coalesced, 32 independent loads
            dot = fmaf(r[j], v, dot);
            nrm = fmaf(v, v, nrm);
        }
        sdot[t] = dot; snrm[t] = nrm;
        __syncthreads();

        if (t < 32) {
            float D = sdot[t], N = snrm[t];
            #pragma unroll
            for (int q2 = 1; q2 < 8; q2++) {  // fixed sequential order (deterministic)
                D += sdot[t + (q2 << 5)];
                N += snrm[t + (q2 << 5)];
            }
            d_sim[(bid << 5) + t] = D / sqrtf(N);
        }
        __syncthreads();
    } else if (bid < NINIT) {
        int idx = (bid - 128) * 256 + t;      // 0..4095
        if (idx == 0) d_minkey = ~0ull;
        if (idx < NCELLS) d_cellkey[idx] = 0ull;

        if (idx < 1024) {                     // 64 -> 1024 taps (P rows and cols)
            Tap tp = make_tap(samplef(idx, 0.0625f), FEAT);
            d_xt1[idx] = make_float4(__int_as_float(tp.i0), tp.w0, tp.w1, 0.f);
        }
        int H = ori[0], W = ori[1];
        int mxv = max(H, W);
        double scale = (double)IMGSZ / (double)mxv;
        int ph = (int)floor((double)H * scale + 0.5);
        int pw = (int)floor((double)W * scale + 0.5);
        float invx = (float)(1.0 / ((double)W / (double)pw));
        float invy = (float)(1.0 / ((double)H / (double)ph));
        float r64  = (float)(scale / 64.0);
        if (idx < W) {                        // scan x-taps (pw -> W)
            Tap tp = make_tap(samplef(idx, invx), pw);
            d_xtab[idx] = make_float4(__int_as_float(tp.i0), tp.w0, tp.w1, 0.f);
        }
        if (idx < H) {                        // scan y-taps (ph -> H) + gy16
            Tap tp = make_tap(samplef(idx, invy), ph);
            int gy16 = 16 * (int)floorf(__fmul_rn((float)idx, r64));
            d_ytab[idx] = make_float4(__int_as_float(tp.i0), tp.w0, tp.w1,
                                      __int_as_float(gy16));
        }
    }

    // signal + grid-internal barrier (all 720 blocks co-resident by launch_bounds)
    if (t == 0) {
        if (bid < NINIT) { __threadfence(); atomicAdd(&d_go, 1); }
        while (*(volatile int*)&d_go < NINIT) __nanosleep(64);
    }
    __syncthreads();

    // ================= phase 2: scan (verbatim R15 logic) =================
    int H = ori[0], W = ori[1];
    int mxv = max(H, W);
    double scale = (double)IMGSZ / (double)mxv;
    float r64  = (float)(scale / 64.0);

    int xs = blockIdx.x * 512;
    int nby = gridDim.y;
    int chn = (H + nby - 1) / nby;             // <= YCHUNK
    int ys = blockIdx.y * chn;
    int ye = min(H, ys + chn);

    unsigned long long localkey = ~0ull;

    if (ys < H && xs < W) {
        int ny = ye - ys;
        int xe = min(xs + 512, W);
        // P-tile bounds this block needs (monotone tap tables)
        int pr0 = __float_as_int(d_ytab[ys].x);
        int pr1 = __float_as_int(d_ytab[ye - 1].x) + 1;
        int px0 = __float_as_int(d_xtab[xs].x);
        int px1 = __float_as_int(d_xtab[xe - 1].x) + 1;
        int NR = pr1 - pr0 + 1;
        int NC = px1 - px0 + 1;

        // stage y-taps for this strip
        for (int i = t; i < ny; i += 256) s_yt[i] = d_ytab[ys + i];

        // build tile2: each entry holds (P(r,c), P(r,c+1)), exact expression
        int nbuild = NR * (NC - 1);
        for (int i = t; i < nbuild; i += 256) {
            int r = i / (NC - 1), c = i - r * (NC - 1);
            float v0 = p_val(pr0 + r, px0 + c);
            float v1 = p_val(pr0 + r, px0 + c + 1);
            tile2[r][c] = make_float2(v0, v1);
        }
        __syncthreads();

        int xa = xs + t;            // column A
        int xb = xa + 256;          // column B
        bool hasB = (xb < W);
        if (xa < W) {
            float4 txA = d_xtab[xa];
            int   lxa  = __float_as_int(txA.x) - px0;
            float wa0 = txA.y, wa1 = txA.z;
            float4 txB = hasB ? d_xtab[xb] : txA;
            int   lxb  = __float_as_int(txB.x) - px0;
            float wb0 = txB.y, wb1 = txB.z;

            // 2 index-tracked chains per column (even/odd y) + one shared max
            float rba0 = INFINITY, rba1 = INFINITY, rbb0 = INFINITY, rbb1 = INFINITY;
            int   ria0 = 0, ria1 = 0, rib0 = 0, rib1 = 0;
            float rmax = -INFINITY;

            int idx0 = ys * W + xa;     // column A index; column B = +256
            int i = 0;
            for (; i + 1 < ny; i += 2) {
                #pragma unroll
                for (int j = 0; j < 2; j++) {
                    float4 ty = s_yt[i + j];
                    int lr = __float_as_int(ty.x) - pr0;
                    const float2* R0 = &tile2[lr][0];
                    const float2* R1 = &tile2[lr + 1][0];
                    float2 A0 = R0[lxa], B0 = R1[lxa];
                    float2 A1 = R0[lxb], B1 = R1[lxb];

                    float ca0 = fmaf(ty.z, B0.x, __fmul_rn(ty.y, A0.x));
                    float ca1 = fmaf(ty.z, B0.y, __fmul_rn(ty.y, A0.y));
                    float va  = fmaf(wa1, ca1, __fmul_rn(wa0, ca0));

                    float cb0 = fmaf(ty.z, B1.x, __fmul_rn(ty.y, A1.x));
                    float cb1 = fmaf(ty.z, B1.y, __fmul_rn(ty.y, A1.y));
                    float vb  = fmaf(wb1, cb1, __fmul_rn(wb0, cb0));

                    int idx = idx0 + j * W;
                    if (j == 0) {
                        if (va < rba0) { rba0 = va; ria0 = idx; }
                        if (vb < rbb0) { rbb0 = vb; rib0 = idx; }
                    } else {
                        if (va < rba1) { rba1 = va; ria1 = idx; }
                        if (vb < rbb1) { rbb1 = vb; rib1 = idx; }
                    }
                    rmax = fmaxf(rmax, fmaxf(va, vb));
                }
                idx0 += 2 * W;
            }
            for (; i < ny; i++) {                // remainder -> chain 0
                float4 ty = s_yt[i];
                int lr = __float_as_int(ty.x) - pr0;
                const float2* R0 = &tile2[lr][0];
                const float2* R1 = &tile2[lr + 1][0];
                float2 A0 = R0[lxa], B0 = R1[lxa];
                float2 A1 = R0[lxb], B1 = R1[lxb];
                float ca0 = fmaf(ty.z, B0.x, __fmul_rn(ty.y, A0.x));
                float ca1 = fmaf(ty.z, B0.y, __fmul_rn(ty.y, A0.y));
                float va  = fmaf(wa1, ca1, __fmul_rn(wa0, ca0));
                float cb0 = fmaf(ty.z, B1.x, __fmul_rn(ty.y, A1.x));
                float cb1 = fmaf(ty.z, B1.y, __fmul_rn(ty.y, A1.y));
                float vb  = fmaf(wb1, cb1, __fmul_rn(wb0, cb0));
                if (va < rba0) { rba0 = va; ria0 = idx0; }
                if (vb < rbb0) { rbb0 = vb; rib0 = idx0; }
                rmax = fmaxf(rmax, fmaxf(va, vb));
                idx0 += W;
            }

            // merge: packed keys, column B indices shifted by +256 (its true x)
            unsigned long long ka0 = ((unsigned long long)fkey(rba0) << 32) | (unsigned)ria0;
            unsigned long long ka1 = ((unsigned long long)fkey(rba1) << 32) | (unsigned)ria1;
            localkey = min(ka0, ka1);
            if (hasB) {
                unsigned long long kb0 = ((unsigned long long)fkey(rbb0) << 32) | (unsigned)(rib0 + 256);
                unsigned long long kb1 = ((unsigned long long)fkey(rbb1) << 32) | (unsigned)(rib1 + 256);
                localkey = min(localkey, min(kb0, kb1));
            }

            // rare slow path: redo both columns with identical values & atomics
            if (rmax > THRESH) {
                int gxa = (int)floorf(__fmul_rn((float)xa, r64));
                int gxb = (int)floorf(__fmul_rn((float)xb, r64));
                int idx = ys * W + xa;
                for (int k = 0; k < ny; k++) {
                    float4 ty = s_yt[k];
                    int lr = __float_as_int(ty.x) - pr0;
                    const float2* R0 = &tile2[lr][0];
                    const float2* R1 = &tile2[lr + 1][0];
                    float2 A0 = R0[lxa], B0 = R1[lxa];
                    float ca0 = fmaf(ty.z, B0.x, __fmul_rn(ty.y, A0.x));
                    float ca1 = fmaf(ty.z, B0.y, __fmul_rn(ty.y, A0.y));
                    float va  = fmaf(wa1, ca1, __fmul_rn(wa0, ca0));
                    if (va > THRESH) {
                        int cell = __float_as_int(ty.w) + gxa;
                        unsigned long long ck = ((unsigned long long)fkey(va) << 32)
                                              | (unsigned)(0xFFFFFFFFu - (unsigned)idx);
                        atomicMax(&d_cellkey[cell], ck);
                    }
                    if (hasB) {
                        float2 A1 = R0[lxb], B1 = R1[lxb];
                        float cb0 = fmaf(ty.z, B1.x, __fmul_rn(ty.y, A1.x));
                        float cb1 = fmaf(ty.z, B1.y, __fmul_rn(ty.y, A1.y));
                        float vb  = fmaf(wb1, cb1, __fmul_rn(wb0, cb0));
                        if (vb > THRESH) {
                            int cell = __float_as_int(ty.w) + gxb;
                            unsigned long long ck = ((unsigned long long)fkey(vb) << 32)
                                                  | (unsigned)(0xFFFFFFFFu - (unsigned)(idx + 256));
                            atomicMax(&d_cellkey[cell], ck);
                        }
                    }
                    idx += W;
                }
            }
        }
    }

    // block argmin reduction
    __shared__ unsigned long long sk[256];
    __shared__ int s_last;
    sk[t] = localkey;
    __syncthreads();
    for (int o = 128; o > 0; o >>= 1) {
        if (t < o) sk[t] = min(sk[t], sk[t + o]);
        __syncthreads();
    }
    if (t == 0) {
        atomicMin(&d_minkey, sk[0]);
        __threadfence();
        s_last = (atomicAdd(&d_counter, 1) == NBLK - 1);
    }
    __syncthreads();
    if (!s_last) return;

    // ---- last block: finalize + reset cross-launch state ----
    __shared__ float s_key[NCELLS];
    unsigned long long ck = atomicOr(&d_cellkey[t], 0ull);    // coherent read
    bool valid = (ck != 0ull);
    float ps = 0.f; int pidx = 0;
    if (valid) {
        ps   = unfkey((unsigned)(ck >> 32));
        pidx = (int)(0xFFFFFFFFu - (unsigned)(ck & 0xFFFFFFFFull));
    }
    float skey = valid ? ps : -INFINITY;
    s_key[t] = skey;
    __syncthreads();

    int rank = 0;
    #pragma unroll 8
    for (int j = 0; j < NCELLS; j++) {
        float o = s_key[j];
        rank += (o > skey) || (o == skey && j < t);
    }

    out[rank * 3 + 0] = valid ? (float)(pidx % W) : -1.f;
    out[rank * 3 + 1] = valid ? (float)(pidx / W) : -1.f;
    out[rank * 3 + 2] = valid ? ps : -1.f;

    if (t == 0) {
        unsigned long long mk = atomicOr(&d_minkey, 0ull);
        unsigned bidx = (unsigned)(mk & 0xFFFFFFFFull);
        out[NCELLS * 3 + 0] = (float)(bidx % (unsigned)W);   // bg col (x)
        out[NCELLS * 3 + 1] = (float)(bidx / (unsigned)W);   // bg row (y)
        d_go = 0;            // reset for next graph replay (all blocks are past the spin)
        d_counter = 0;
    }
}

// ---------------- launch ----------------
extern "C" void kernel_launch(void* const* d_in, const int* in_sizes, int n_in,
                              void* d_out, int out_size) {
    int ie = 0, ir = 1, io = 2;
    for (int i = 0; i < n_in; i++) {
        if (in_sizes[i] == 2) io = i;
        else if (in_sizes[i] == EMBC) ir = i;
        else ie = i;
    }
    const float* emb = (const float*)d_in[ie];
    const float* ref = (const float*)d_in[ir];
    const int*   ori = (const int*)d_in[io];
    float* out = (float*)d_out;

    k_all<<<dim3(SCAN_BX, SCAN_BY), 256>>>(emb, ref, ori, out);
}